// round 1
// baseline (speedup 1.0000x reference)
#include <cuda_runtime.h>
#include <math_constants.h>

#define BLOCK 256
#define CHUNK 1024          // pos2 points per block (one chunk per blockIdx.y)
#define MAX_CHUNKS 32
#define MAX_N1 16384
#define MAX_RED_BLOCKS 64

// Scratch (static device globals — no allocation in kernel_launch)
__device__ float g_partial[MAX_CHUNKS * MAX_N1];   // squared-min per (chunk, pos1)
__device__ float g_blocksums[MAX_RED_BLOCKS];

// ---------------- packed f32x2 helpers (sm_100+ PTX) ----------------
__device__ __forceinline__ unsigned long long f32x2_add(unsigned long long a, unsigned long long b) {
    unsigned long long r;
    asm("add.rn.f32x2 %0, %1, %2;" : "=l"(r) : "l"(a), "l"(b));
    return r;
}
__device__ __forceinline__ unsigned long long f32x2_mul(unsigned long long a, unsigned long long b) {
    unsigned long long r;
    asm("mul.rn.f32x2 %0, %1, %2;" : "=l"(r) : "l"(a), "l"(b));
    return r;
}
__device__ __forceinline__ unsigned long long f32x2_fma(unsigned long long a, unsigned long long b,
                                                        unsigned long long c) {
    unsigned long long r;
    asm("fma.rn.f32x2 %0, %1, %2, %3;" : "=l"(r) : "l"(a), "l"(b), "l"(c));
    return r;
}
__device__ __forceinline__ unsigned long long f32x2_pack(float lo, float hi) {
    unsigned long long r;
    asm("mov.b64 %0, {%1, %2};" : "=l"(r) : "f"(lo), "f"(hi));
    return r;
}
__device__ __forceinline__ float f32x2_lo(unsigned long long v) {
    return __uint_as_float((unsigned int)(v & 0xffffffffull));
}
__device__ __forceinline__ float f32x2_hi(unsigned long long v) {
    return __uint_as_float((unsigned int)(v >> 32));
}

// ---------------- kernel 1: per-(chunk, pos1) squared min ----------------
// Each thread owns TWO pos1 points packed as f32x2. pos2 chunk staged in
// shared, pre-negated and duplicated into both halves of a b64 so the
// subtraction becomes a single packed add. All lanes read the same shared
// address (broadcast, conflict-free).
__global__ void __launch_bounds__(BLOCK) nn_partial_kernel(
    const float* __restrict__ pos1,
    const float* __restrict__ pos2,
    int N1, int N2)
{
    __shared__ __align__(16) unsigned long long s_nx[CHUNK];
    __shared__ __align__(16) unsigned long long s_ny[CHUNK];

    const int chunk = blockIdx.y;
    const int jbase = chunk * CHUNK;

    // Stage chunk of pos2: store (-x,-x) and (-y,-y) packed.
    for (int j = threadIdx.x; j < CHUNK; j += BLOCK) {
        const int gj = jbase + j;
        float nx, ny;
        if (gj < N2) {
            nx = -pos2[2 * gj + 0];
            ny = -pos2[2 * gj + 1];
        } else {
            // padding point far away -> squared distance = +inf, never wins min
            nx = 1e18f;
            ny = 1e18f;
        }
        const unsigned int xb = __float_as_uint(nx);
        const unsigned int yb = __float_as_uint(ny);
        s_nx[j] = ((unsigned long long)xb << 32) | xb;
        s_ny[j] = ((unsigned long long)yb << 32) | yb;
    }
    __syncthreads();

    const int t = blockIdx.x * BLOCK + threadIdx.x;   // pair index
    const int i0 = t * 2;
    if (i0 >= N1) return;

    // two consecutive pos1 points: float4 = (xa, ya, xb, yb)
    const float4 p = reinterpret_cast<const float4*>(pos1)[t];
    const unsigned long long x1p = f32x2_pack(p.x, p.z);
    const unsigned long long y1p = f32x2_pack(p.y, p.w);

    float m0 = CUDART_INF_F;
    float m1 = CUDART_INF_F;

    const ulonglong2* __restrict__ nx2 = reinterpret_cast<const ulonglong2*>(s_nx);
    const ulonglong2* __restrict__ ny2 = reinterpret_cast<const ulonglong2*>(s_ny);

#pragma unroll 8
    for (int j = 0; j < CHUNK / 2; j++) {
        const ulonglong2 nx = nx2[j];   // LDS.128: pos2 j0 and j1 x-pairs
        const ulonglong2 ny = ny2[j];

        // j0
        {
            const unsigned long long dx = f32x2_add(x1p, nx.x);
            const unsigned long long dy = f32x2_add(y1p, ny.x);
            const unsigned long long d2 = f32x2_fma(dx, dx, f32x2_mul(dy, dy));
            m0 = fminf(m0, f32x2_lo(d2));
            m1 = fminf(m1, f32x2_hi(d2));
        }
        // j1
        {
            const unsigned long long dx = f32x2_add(x1p, nx.y);
            const unsigned long long dy = f32x2_add(y1p, ny.y);
            const unsigned long long d2 = f32x2_fma(dx, dx, f32x2_mul(dy, dy));
            m0 = fminf(m0, f32x2_lo(d2));
            m1 = fminf(m1, f32x2_hi(d2));
        }
    }

    g_partial[chunk * N1 + i0 + 0] = m0;
    g_partial[chunk * N1 + i0 + 1] = m1;
}

// ---------------- kernel 2: min across chunks, sqrt, block partial sums ----
__global__ void __launch_bounds__(256) nn_reduce_kernel(int N1, int nchunks)
{
    const int i = blockIdx.x * blockDim.x + threadIdx.x;
    float v = 0.0f;
    if (i < N1) {
        float m = CUDART_INF_F;
        for (int c = 0; c < nchunks; c++)
            m = fminf(m, g_partial[c * N1 + i]);
        v = sqrtf(m);
    }
    __shared__ float red[256];
    red[threadIdx.x] = v;
    __syncthreads();
#pragma unroll
    for (int s = 128; s > 0; s >>= 1) {
        if (threadIdx.x < s) red[threadIdx.x] += red[threadIdx.x + s];
        __syncthreads();
    }
    if (threadIdx.x == 0) g_blocksums[blockIdx.x] = red[0];
}

// ---------------- kernel 3: final deterministic sum + mean ----------------
__global__ void nn_final_kernel(float* __restrict__ out, int nblocks, float inv_n)
{
    __shared__ float red[64];
    float v = (threadIdx.x < nblocks) ? g_blocksums[threadIdx.x] : 0.0f;
    red[threadIdx.x] = v;
    __syncthreads();
#pragma unroll
    for (int s = 32; s > 0; s >>= 1) {
        if (threadIdx.x < s) red[threadIdx.x] += red[threadIdx.x + s];
        __syncthreads();
    }
    if (threadIdx.x == 0) out[0] = red[0] * inv_n;
}

// ---------------- launch ----------------
extern "C" void kernel_launch(void* const* d_in, const int* in_sizes, int n_in,
                              void* d_out, int out_size)
{
    const float* pos1 = (const float*)d_in[0];
    const float* pos2 = (const float*)d_in[1];
    float* out = (float*)d_out;

    const int N1 = in_sizes[0] / 2;
    const int N2 = in_sizes[1] / 2;

    int nchunks = (N2 + CHUNK - 1) / CHUNK;
    if (nchunks > MAX_CHUNKS) nchunks = MAX_CHUNKS;   // shapes fixed at 16384 -> 16

    const int pairs = (N1 + 1) / 2;                   // threads needed (2 pos1 each)
    dim3 grid1((pairs + BLOCK - 1) / BLOCK, nchunks);
    nn_partial_kernel<<<grid1, BLOCK>>>(pos1, pos2, N1, N2);

    const int red_blocks = (N1 + 255) / 256;          // 64 for N1=16384
    nn_reduce_kernel<<<red_blocks, 256>>>(N1, nchunks);

    nn_final_kernel<<<1, 64>>>(out, red_blocks, 1.0f / (float)N1);
}

// round 2
// speedup vs baseline: 1.2256x; 1.2256x over previous
#include <cuda_runtime.h>
#include <math_constants.h>

#define BLOCK 256
#define CHUNK 448            // pos2 points per chunk (37 chunks for N2=16384)
#define MAX_CHUNKS 64
#define MAX_N1 16384
#define MAX_RED_BLOCKS 64

// Scratch (static device globals — no allocation in kernel_launch)
__device__ float g_partial[MAX_CHUNKS * MAX_N1];   // min_j (|p2|^2 - 2 p1.p2) per (chunk, pos1)
__device__ float g_blocksums[MAX_RED_BLOCKS];

// ---------------- packed f32x2 helpers (sm_100+ PTX) ----------------
__device__ __forceinline__ unsigned long long f32x2_fma(unsigned long long a, unsigned long long b,
                                                        unsigned long long c) {
    unsigned long long r;
    asm("fma.rn.f32x2 %0, %1, %2, %3;" : "=l"(r) : "l"(a), "l"(b), "l"(c));
    return r;
}
__device__ __forceinline__ unsigned long long f32x2_pack(float lo, float hi) {
    unsigned long long r;
    asm("mov.b64 %0, {%1, %2};" : "=l"(r) : "f"(lo), "f"(hi));
    return r;
}
__device__ __forceinline__ float f32x2_lo(unsigned long long v) {
    float lo, hi;
    asm("mov.b64 {%0, %1}, %2;" : "=f"(lo), "=f"(hi) : "l"(v));
    return lo;
}
__device__ __forceinline__ float f32x2_hi(unsigned long long v) {
    float lo, hi;
    asm("mov.b64 {%0, %1}, %2;" : "=f"(lo), "=f"(hi) : "l"(v));
    return hi;
}

// ---------------- kernel 1: per-(chunk, pos1) min of (|p2|^2 - 2 p1.p2) ----
// Each thread owns FOUR pos1 points (two f32x2 pairs). pos2 chunk staged in
// shared as three duplicated-b64 arrays: nx=(-2x,-2x), ny=(-2y,-2y),
// c=(|p2|^2,|p2|^2). Per pos2 point per pos1-pair the inner loop is exactly
// two packed FMAs; mins go to the alu pipe (FMNMX), concurrent with fma pipe.
__global__ void __launch_bounds__(BLOCK) nn_partial_kernel(
    const float* __restrict__ pos1,
    const float* __restrict__ pos2,
    int N1, int N2)
{
    __shared__ __align__(16) unsigned long long s_nx[CHUNK];
    __shared__ __align__(16) unsigned long long s_ny[CHUNK];
    __shared__ __align__(16) unsigned long long s_c[CHUNK];

    const int chunk = blockIdx.y;
    const int jbase = chunk * CHUNK;

    for (int j = threadIdx.x; j < CHUNK; j += BLOCK) {
        const int gj = jbase + j;
        float nx, ny, c;
        if (gj < N2) {
            const float x = pos2[2 * gj + 0];
            const float y = pos2[2 * gj + 1];
            nx = -2.0f * x;
            ny = -2.0f * y;
            c  = x * x + y * y;
        } else {
            nx = 0.0f; ny = 0.0f; c = 1e30f;   // padding never wins the min
        }
        const unsigned long long xb = (unsigned long long)__float_as_uint(nx);
        const unsigned long long yb = (unsigned long long)__float_as_uint(ny);
        const unsigned long long cb = (unsigned long long)__float_as_uint(c);
        s_nx[j] = (xb << 32) | xb;
        s_ny[j] = (yb << 32) | yb;
        s_c[j]  = (cb << 32) | cb;
    }
    __syncthreads();

    const int t = blockIdx.x * BLOCK + threadIdx.x;   // quad index
    const int i0 = t * 4;
    if (i0 >= N1) return;

    // four consecutive pos1 points: two float4 loads
    unsigned long long x1p0, y1p0, x1p1, y1p1;
    if (i0 + 3 < N1) {
        const float4 pa = reinterpret_cast<const float4*>(pos1)[t * 2 + 0];
        const float4 pb = reinterpret_cast<const float4*>(pos1)[t * 2 + 1];
        x1p0 = f32x2_pack(pa.x, pa.z);
        y1p0 = f32x2_pack(pa.y, pa.w);
        x1p1 = f32x2_pack(pb.x, pb.z);
        y1p1 = f32x2_pack(pb.y, pb.w);
    } else {
        float xs[4], ys[4];
        for (int k = 0; k < 4; k++) {
            const int gi = (i0 + k < N1) ? (i0 + k) : (N1 - 1);
            xs[k] = pos1[2 * gi + 0];
            ys[k] = pos1[2 * gi + 1];
        }
        x1p0 = f32x2_pack(xs[0], xs[1]);
        y1p0 = f32x2_pack(ys[0], ys[1]);
        x1p1 = f32x2_pack(xs[2], xs[3]);
        y1p1 = f32x2_pack(ys[2], ys[3]);
    }

    float m0 = CUDART_INF_F, m1 = CUDART_INF_F;
    float m2 = CUDART_INF_F, m3 = CUDART_INF_F;

    const ulonglong2* __restrict__ nx2 = reinterpret_cast<const ulonglong2*>(s_nx);
    const ulonglong2* __restrict__ ny2 = reinterpret_cast<const ulonglong2*>(s_ny);
    const ulonglong2* __restrict__ c2  = reinterpret_cast<const ulonglong2*>(s_c);

#pragma unroll 4
    for (int j = 0; j < CHUNK / 2; j++) {
        const ulonglong2 nx = nx2[j];   // LDS.128 each, lane-broadcast
        const ulonglong2 ny = ny2[j];
        const ulonglong2 cc = c2[j];

        // pos2 point j0
        {
            const unsigned long long s0 = f32x2_fma(y1p0, ny.x, f32x2_fma(x1p0, nx.x, cc.x));
            const unsigned long long s1 = f32x2_fma(y1p1, ny.x, f32x2_fma(x1p1, nx.x, cc.x));
            m0 = fminf(m0, f32x2_lo(s0));
            m1 = fminf(m1, f32x2_hi(s0));
            m2 = fminf(m2, f32x2_lo(s1));
            m3 = fminf(m3, f32x2_hi(s1));
        }
        // pos2 point j1
        {
            const unsigned long long s0 = f32x2_fma(y1p0, ny.y, f32x2_fma(x1p0, nx.y, cc.y));
            const unsigned long long s1 = f32x2_fma(y1p1, ny.y, f32x2_fma(x1p1, nx.y, cc.y));
            m0 = fminf(m0, f32x2_lo(s0));
            m1 = fminf(m1, f32x2_hi(s0));
            m2 = fminf(m2, f32x2_lo(s1));
            m3 = fminf(m3, f32x2_hi(s1));
        }
    }

    if (i0 + 3 < N1) {
        float4 o; o.x = m0; o.y = m1; o.z = m2; o.w = m3;
        reinterpret_cast<float4*>(&g_partial[chunk * N1 + i0])[0] = o;
    } else {
        float mv[4] = {m0, m1, m2, m3};
        for (int k = 0; k < 4 && i0 + k < N1; k++)
            g_partial[chunk * N1 + i0 + k] = mv[k];
    }
}

// ---- kernel 2: min across chunks, add |p1|^2, sqrt, block partial sums ----
__global__ void __launch_bounds__(256) nn_reduce_kernel(
    const float* __restrict__ pos1, int N1, int nchunks)
{
    const int i = blockIdx.x * blockDim.x + threadIdx.x;
    float v = 0.0f;
    if (i < N1) {
        float m = CUDART_INF_F;
        for (int c = 0; c < nchunks; c++)
            m = fminf(m, g_partial[c * N1 + i]);
        const float x = pos1[2 * i + 0];
        const float y = pos1[2 * i + 1];
        const float d2 = m + (x * x + y * y);
        v = sqrtf(fmaxf(d2, 0.0f));
    }
    __shared__ float red[256];
    red[threadIdx.x] = v;
    __syncthreads();
#pragma unroll
    for (int s = 128; s > 0; s >>= 1) {
        if (threadIdx.x < s) red[threadIdx.x] += red[threadIdx.x + s];
        __syncthreads();
    }
    if (threadIdx.x == 0) g_blocksums[blockIdx.x] = red[0];
}

// ---------------- kernel 3: final deterministic sum + mean ----------------
__global__ void nn_final_kernel(float* __restrict__ out, int nblocks, float inv_n)
{
    __shared__ float red[64];
    float v = (threadIdx.x < nblocks) ? g_blocksums[threadIdx.x] : 0.0f;
    red[threadIdx.x] = v;
    __syncthreads();
#pragma unroll
    for (int s = 32; s > 0; s >>= 1) {
        if (threadIdx.x < s) red[threadIdx.x] += red[threadIdx.x + s];
        __syncthreads();
    }
    if (threadIdx.x == 0) out[0] = red[0] * inv_n;
}

// ---------------- launch ----------------
extern "C" void kernel_launch(void* const* d_in, const int* in_sizes, int n_in,
                              void* d_out, int out_size)
{
    const float* pos1 = (const float*)d_in[0];
    const float* pos2 = (const float*)d_in[1];
    float* out = (float*)d_out;

    const int N1 = in_sizes[0] / 2;
    const int N2 = in_sizes[1] / 2;

    int nchunks = (N2 + CHUNK - 1) / CHUNK;           // 37 for N2=16384
    if (nchunks > MAX_CHUNKS) nchunks = MAX_CHUNKS;

    const int quads = (N1 + 3) / 4;                   // threads (4 pos1 each)
    dim3 grid1((quads + BLOCK - 1) / BLOCK, nchunks); // 16 x 37 = 592 = 4 * 148
    nn_partial_kernel<<<grid1, BLOCK>>>(pos1, pos2, N1, N2);

    const int red_blocks = (N1 + 255) / 256;          // 64 for N1=16384
    nn_reduce_kernel<<<red_blocks, 256>>>(pos1, N1, nchunks);

    nn_final_kernel<<<1, 64>>>(out, red_blocks, 1.0f / (float)N1);
}